// round 6
// baseline (speedup 1.0000x reference)
#include <cuda_runtime.h>
#include <cuda_fp16.h>
#include <cstdint>

// ============================================================================
// y[M,N] = x[M,K] @ (qw*sw)^T + bias   M=8192, N=4096, K=4096
// x fp32, qw int32 (int8 values), sw fp32 scalar, bias fp32[N], out fp32.
//
// R5: dual-int8 IMMA path (mma.sync.m16n8k32.s8 — generic PTX, works on
// compute_103 target). HMMA floor measured ~12 cyc/instr; IMMA carries 2x
// MACs/instr at (expected) equal rt => ~2x GEMM speedup.
//   x = s1*q1 + s2*q2 (int8 split, s2=s1/252)  -> quant noise ~5e-5
//   w exact int8. int32 accumulation EXACT.
//   y = sw*(s1*acc1 + s2*acc2) + bias
// ============================================================================

#define MDIM 8192
#define NDIM 4096
#define KDIM 4096

#define BM 128
#define BN 128
#define BK 128                        // int8 elements per stage (128 B rows)
#define STAGES 4
#define KITERS (KDIM / BK)            // 32

#define ROW_BYTES 144                 // 128 B data + 16 pad (conflict-free)
#define TILE_BYTES (128 * ROW_BYTES)  // 18432 per tile (Aq1 / Aq2 / W)
#define STAGE_BYTES (3 * TILE_BYTES)  // 55296
#define SMEM_TOTAL (STAGES * STAGE_BYTES)  // 221184 < 228KB

// ---------------- scratch (static device globals: allocation-free) ----------
__device__ int8_t g_q1[(size_t)MDIM * KDIM];   // 32 MB
__device__ int8_t g_q2[(size_t)MDIM * KDIM];   // 32 MB
__device__ int8_t g_w8[(size_t)NDIM * KDIM];   // 16 MB
__device__ unsigned g_amax_bits;

// ---------------- pre-pass kernels ------------------------------------------
__global__ void init_amax_kernel() { g_amax_bits = 0u; }

__global__ __launch_bounds__(256) void amax_kernel(const float* __restrict__ x) {
    const size_t n4 = (size_t)MDIM * KDIM / 4;
    const size_t stride = (size_t)gridDim.x * blockDim.x;
    float m = 0.f;
    for (size_t i = (size_t)blockIdx.x * blockDim.x + threadIdx.x; i < n4; i += stride) {
        const float4 v = reinterpret_cast<const float4*>(x)[i];
        m = fmaxf(m, fmaxf(fmaxf(fabsf(v.x), fabsf(v.y)), fmaxf(fabsf(v.z), fabsf(v.w))));
    }
#pragma unroll
    for (int o = 16; o > 0; o >>= 1)
        m = fmaxf(m, __shfl_xor_sync(0xFFFFFFFFu, m, o));
    if ((threadIdx.x & 31) == 0)
        atomicMax(&g_amax_bits, __float_as_uint(m));  // m >= 0: uint order == float order
}

// x -> q1,q2 int8 split. Each thread: 16 floats -> 16B q1 + 16B q2.
__global__ __launch_bounds__(256) void quant_x_kernel(const float* __restrict__ x) {
    const float amax = __uint_as_float(g_amax_bits);
    const float s1 = amax / 126.f;
    const float inv1 = (amax > 0.f) ? 126.f / amax : 0.f;
    const float inv2 = (amax > 0.f) ? 31752.f / amax : 0.f;  // 1/s2, s2 = s1/252
    const size_t t = (size_t)blockIdx.x * blockDim.x + threadIdx.x;
    uint32_t p1[4], p2[4];
#pragma unroll
    for (int c = 0; c < 4; ++c) {
        const float4 v = reinterpret_cast<const float4*>(x)[t * 4 + c];
        const float f[4] = {v.x, v.y, v.z, v.w};
        uint32_t a1 = 0, a2 = 0;
#pragma unroll
        for (int j = 0; j < 4; ++j) {
            const float q1f = rintf(f[j] * inv1);
            const float r = fmaf(-s1, q1f, f[j]);
            const int q1 = (int)q1f;
            const int q2 = (int)rintf(r * inv2);
            a1 |= (uint32_t)(q1 & 0xff) << (8 * j);
            a2 |= (uint32_t)(q2 & 0xff) << (8 * j);
        }
        p1[c] = a1; p2[c] = a2;
    }
    reinterpret_cast<uint4*>(g_q1)[t] = make_uint4(p1[0], p1[1], p1[2], p1[3]);
    reinterpret_cast<uint4*>(g_q2)[t] = make_uint4(p2[0], p2[1], p2[2], p2[3]);
}

// qw int32 -> int8 (exact). Each thread: 16 ints -> 16 bytes.
__global__ __launch_bounds__(256) void convert_w_kernel(const int* __restrict__ qw) {
    const size_t t = (size_t)blockIdx.x * blockDim.x + threadIdx.x;
    uint32_t p[4];
#pragma unroll
    for (int c = 0; c < 4; ++c) {
        const int4 v = reinterpret_cast<const int4*>(qw)[t * 4 + c];
        p[c] = (uint32_t)(v.x & 0xff) | ((uint32_t)(v.y & 0xff) << 8) |
               ((uint32_t)(v.z & 0xff) << 16) | ((uint32_t)(v.w & 0xff) << 24);
    }
    reinterpret_cast<uint4*>(g_w8)[t] = make_uint4(p[0], p[1], p[2], p[3]);
}

// ---------------- GEMM kernel ------------------------------------------------
__global__ __launch_bounds__(256, 1) void gemm_kernel(
    float* __restrict__ out,
    const float* __restrict__ swp,
    const float* __restrict__ bias) {
    extern __shared__ char smem[];

    const int tid = threadIdx.x;
    const int lane = tid & 31;
    const int wid = tid >> 5;
    const int wm = (wid & 3) * 32;    // 4 warps in m, warp tile 32 rows
    const int wn = (wid >> 2) * 64;   // 2 warps in n, warp tile 64 cols
    const int m0 = blockIdx.y * BM;
    const int n0 = blockIdx.x * BN;

    const uint32_t sbase = (uint32_t)__cvta_generic_to_shared(smem);

    const int8_t* gQ1 = g_q1 + (size_t)m0 * KDIM;
    const int8_t* gQ2 = g_q2 + (size_t)m0 * KDIM;
    const int8_t* gW = g_w8 + (size_t)n0 * KDIM;

    int acc1[2][8][4], acc2[2][8][4];
#pragma unroll
    for (int mi = 0; mi < 2; ++mi)
#pragma unroll
        for (int n = 0; n < 8; ++n)
#pragma unroll
            for (int j = 0; j < 4; ++j) { acc1[mi][n][j] = 0; acc2[mi][n][j] = 0; }

    // ldmatrix lane offset: mat0 rows0-7 k[0:16), mat1 rows8-15 k[0:16),
    //                       mat2 rows0-7 k[16:32), mat3 rows8-15 k[16:32)
    const uint32_t lrow = ((lane >> 3) & 1) * 8 + (lane & 7);
    const uint32_t lkb = (lane >> 4) * 16;
    const uint32_t lm_off = lrow * ROW_BYTES + lkb;

    // ---- producer: load stage `s` with k-tile `it` (all 256 threads) --------
    auto load_tile = [&](int it, int s) {
        const int k0 = it * BK;
        const uint32_t base = sbase + s * STAGE_BYTES;
#pragma unroll
        for (int i = 0; i < 4; ++i) {   // 1024 chunks per tile, 4/thread
            const int c = tid + i * 256;
            const int r = c >> 3, cc = c & 7;
            const uint32_t off = (uint32_t)(r * ROW_BYTES + cc * 16);
            const size_t ge = (size_t)r * KDIM + k0 + cc * 16;
            const size_t gw = (size_t)r * KDIM + k0 + cc * 16;
            asm volatile("cp.async.cg.shared.global [%0], [%1], 16;"
                         :: "r"(base + off), "l"(__cvta_generic_to_global(gQ1 + ge)) : "memory");
            asm volatile("cp.async.cg.shared.global [%0], [%1], 16;"
                         :: "r"(base + TILE_BYTES + off), "l"(__cvta_generic_to_global(gQ2 + ge)) : "memory");
            asm volatile("cp.async.cg.shared.global [%0], [%1], 16;"
                         :: "r"(base + 2 * TILE_BYTES + off), "l"(__cvta_generic_to_global(gW + gw)) : "memory");
        }
        asm volatile("cp.async.commit_group;" ::: "memory");
    };

    // frag loaders for one kstep (kb = ks*32 bytes along K)
    auto load_frags = [&](uint32_t base, int ks, uint32_t a1[2][4], uint32_t a2[2][4],
                          uint32_t b[4][4]) {
        const uint32_t kb = (uint32_t)ks * 32;
#pragma unroll
        for (int mi = 0; mi < 2; ++mi) {
            const uint32_t ad1 = base + (wm + mi * 16) * ROW_BYTES + lm_off + kb;
            asm volatile("ldmatrix.sync.aligned.m8n8.x4.shared.b16 {%0,%1,%2,%3}, [%4];"
                         : "=r"(a1[mi][0]), "=r"(a1[mi][1]), "=r"(a1[mi][2]), "=r"(a1[mi][3])
                         : "r"(ad1));
            const uint32_t ad2 = base + TILE_BYTES + (wm + mi * 16) * ROW_BYTES + lm_off + kb;
            asm volatile("ldmatrix.sync.aligned.m8n8.x4.shared.b16 {%0,%1,%2,%3}, [%4];"
                         : "=r"(a2[mi][0]), "=r"(a2[mi][1]), "=r"(a2[mi][2]), "=r"(a2[mi][3])
                         : "r"(ad2));
        }
#pragma unroll
        for (int nj = 0; nj < 4; ++nj) {
            const uint32_t bd = base + 2 * TILE_BYTES + (wn + nj * 16) * ROW_BYTES + lm_off + kb;
            asm volatile("ldmatrix.sync.aligned.m8n8.x4.shared.b16 {%0,%1,%2,%3}, [%4];"
                         : "=r"(b[nj][0]), "=r"(b[nj][1]), "=r"(b[nj][2]), "=r"(b[nj][3])
                         : "r"(bd));
        }
    };

    auto do_mmas = [&](uint32_t a1[2][4], uint32_t a2[2][4], uint32_t b[4][4]) {
#pragma unroll
        for (int mi = 0; mi < 2; ++mi) {
#pragma unroll
            for (int n = 0; n < 8; ++n) {
                const uint32_t b0 = b[n >> 1][n & 1];
                const uint32_t b1 = b[n >> 1][(n & 1) + 2];
                int* c1 = acc1[mi][n];
                asm volatile(
                    "mma.sync.aligned.m16n8k32.row.col.s32.s8.s8.s32 "
                    "{%0,%1,%2,%3}, {%4,%5,%6,%7}, {%8,%9}, {%0,%1,%2,%3};"
                    : "+r"(c1[0]), "+r"(c1[1]), "+r"(c1[2]), "+r"(c1[3])
                    : "r"(a1[mi][0]), "r"(a1[mi][1]), "r"(a1[mi][2]), "r"(a1[mi][3]),
                      "r"(b0), "r"(b1));
                int* c2 = acc2[mi][n];
                asm volatile(
                    "mma.sync.aligned.m16n8k32.row.col.s32.s8.s8.s32 "
                    "{%0,%1,%2,%3}, {%4,%5,%6,%7}, {%8,%9}, {%0,%1,%2,%3};"
                    : "+r"(c2[0]), "+r"(c2[1]), "+r"(c2[2]), "+r"(c2[3])
                    : "r"(a2[mi][0]), "r"(a2[mi][1]), "r"(a2[mi][2]), "r"(a2[mi][3]),
                      "r"(b0), "r"(b1));
            }
        }
    };

    // ---- prologue -----------------------------------------------------------
    load_tile(0, 0);
    load_tile(1, 1);
    load_tile(2, 2);

    uint32_t af1[2][2][4], af2[2][2][4], bf[2][4][4];

    // ---- mainloop: one sync per iter, frag double-buffer --------------------
    for (int it = 0; it < KITERS; ++it) {
        asm volatile("cp.async.wait_group %0;" :: "n"(STAGES - 2) : "memory");
        __syncthreads();

        const int nt = it + (STAGES - 1);
        if (nt < KITERS) load_tile(nt, nt & (STAGES - 1));
        else asm volatile("cp.async.commit_group;" ::: "memory");

        const uint32_t base = sbase + (it & (STAGES - 1)) * STAGE_BYTES;

        load_frags(base, 0, af1[0], af2[0], bf[0]);
#pragma unroll
        for (int ks = 0; ks < BK / 32; ++ks) {       // 4 ksteps of k=32
            if (ks < BK / 32 - 1)
                load_frags(base, ks + 1, af1[(ks + 1) & 1], af2[(ks + 1) & 1], bf[(ks + 1) & 1]);
            do_mmas(af1[ks & 1], af2[ks & 1], bf[ks & 1]);
        }
    }

    // ---- epilogue: y = sw*(s1*acc1 + s2*acc2) + bias ------------------------
    const float amax = __uint_as_float(g_amax_bits);
    const float s1 = amax / 126.f;
    const float s2 = s1 / 252.f;
    const float swv = *swp;
#pragma unroll
    for (int mi = 0; mi < 2; ++mi) {
        const int mr = m0 + wm + mi * 16 + (lane >> 2);
        float* r0 = out + (size_t)mr * NDIM;
        float* r1 = out + (size_t)(mr + 8) * NDIM;
#pragma unroll
        for (int n = 0; n < 8; ++n) {
            const int nc = n0 + wn + n * 8 + (lane & 3) * 2;
            const float2 bv = *reinterpret_cast<const float2*>(bias + nc);
            float2 v0, v1;
            v0.x = fmaf(s1 * (float)acc1[mi][n][0] + s2 * (float)acc2[mi][n][0], swv, bv.x);
            v0.y = fmaf(s1 * (float)acc1[mi][n][1] + s2 * (float)acc2[mi][n][1], swv, bv.y);
            v1.x = fmaf(s1 * (float)acc1[mi][n][2] + s2 * (float)acc2[mi][n][2], swv, bv.x);
            v1.y = fmaf(s1 * (float)acc1[mi][n][3] + s2 * (float)acc2[mi][n][3], swv, bv.y);
            *reinterpret_cast<float2*>(r0 + nc) = v0;
            *reinterpret_cast<float2*>(r1 + nc) = v1;
        }
    }
}

// ---------------- launch -----------------------------------------------------
extern "C" void kernel_launch(void* const* d_in, const int* in_sizes, int n_in,
                              void* d_out, int out_size) {
    const float* x = (const float*)d_in[0];
    const int* qw = (const int*)d_in[1];
    const float* sw = (const float*)d_in[2];
    const float* bias = (const float*)d_in[3];
    float* out = (float*)d_out;
    (void)in_sizes; (void)n_in; (void)out_size;

    cudaFuncSetAttribute(gemm_kernel, cudaFuncAttributeMaxDynamicSharedMemorySize, SMEM_TOTAL);

    init_amax_kernel<<<1, 1>>>();
    amax_kernel<<<1184, 256>>>(x);                                  // 8*148 blocks
    quant_x_kernel<<<(int)((size_t)MDIM * KDIM / 16 / 256), 256>>>(x);
    convert_w_kernel<<<(int)((size_t)NDIM * KDIM / 16 / 256), 256>>>(qw);

    dim3 grid(NDIM / BN, MDIM / BM);  // (32, 64)
    gemm_kernel<<<grid, 256, SMEM_TOTAL>>>(out, sw, bias);
}

// round 10
// speedup vs baseline: 5.5640x; 5.5640x over previous
#include <cuda_runtime.h>
#include <cuda_fp16.h>
#include <cstdint>

// ============================================================================
// y[M,N] = x[M,K] @ (qw*sw)^T + bias   M=8192, N=4096, K=4096
// x fp32, qw int32 (int8 values), sw fp32 scalar, bias fp32[N], out fp32.
//
// compute_103 target (no tcgen05) => mma.sync.m16n8k16 fp16 / fp32 accum.
// Weights EXACT in fp16 (|q|<=128); x->fp16 gives rel_err ~2e-4 < 1e-3.
//
// R9 = R6 with the deadlock fixed:
//   cp.async.mbarrier.arrive  ->  cp.async.mbarrier.arrive.NOINC
// (non-noinc increments-then-satisfies its own pending count: net-zero vs the
//  init count of 256, so the full barrier never flipped -> R6 hang.)
// Waits use the suspend-hint try_wait form (HW sleep, not hot spin).
// ============================================================================

#define MDIM 8192
#define NDIM 4096
#define KDIM 4096

#define BM 128
#define BN 256
#define BK 64
#define STAGES 4
#define KITERS (KDIM / BK)          // 64

#define ROW_HALFS (BK + 8)           // 72 halfs = 144 B (conflict-free ldmatrix)
#define ROW_BYTES (ROW_HALFS * 2)
#define A_STAGE_BYTES (BM * ROW_BYTES)             // 18432
#define B_STAGE_BYTES (BN * ROW_BYTES)             // 36864
#define STAGE_BYTES (A_STAGE_BYTES + B_STAGE_BYTES)  // 55296
#define SMEM_TOTAL (STAGES * STAGE_BYTES)            // 221184 B

// ---------------- scratch (static device globals: allocation-free) ----------
__device__ __half g_xh[(size_t)MDIM * KDIM];  // 64 MB
__device__ __half g_w[(size_t)NDIM * KDIM];   // 32 MB

// ---------------- mbarrier helpers (sm_80+ generic PTX) ----------------------
#define MBAR_INIT(addr, count) \
    asm volatile("mbarrier.init.shared.b64 [%0], %1;" \
        :: "r"((uint32_t)(addr)), "r"((uint32_t)(count)) : "memory")

#define MBAR_ARRIVE(addr) \
    asm volatile("mbarrier.arrive.shared.b64 _, [%0];" :: "r"((uint32_t)(addr)) : "memory")

// NOINC: the completion arrive COUNTS against the init count (256).
#define CPASYNC_MBAR_ARRIVE_NOINC(addr) \
    asm volatile("cp.async.mbarrier.arrive.noinc.shared.b64 [%0];" \
        :: "r"((uint32_t)(addr)) : "memory")

#define MBAR_WAIT_PARITY(mbar_addr, phase_parity) do { \
    uint32_t _mbar = (uint32_t)(mbar_addr); \
    uint32_t _par = (uint32_t)(phase_parity); \
    uint32_t _done; \
    asm volatile( \
        "{\n\t.reg .pred p;\n\t" \
        "mbarrier.try_wait.parity.shared.b64 p, [%1], %2, 0x989680;\n\t" \
        "selp.b32 %0, 1, 0, p;\n\t}" \
        : "=r"(_done) : "r"(_mbar), "r"(_par) : "memory"); \
    if (!_done) { \
        asm volatile( \
            "{\n\t.reg .pred P1;\n\t" \
            "WL_%=:\n\t" \
            "mbarrier.try_wait.parity.shared.b64 P1, [%0], %1, 0x989680;\n\t" \
            "@P1 bra.uni WD_%=;\n\t" \
            "bra.uni WL_%=;\n\t" \
            "WD_%=:\n\t}" \
            :: "r"(_mbar), "r"(_par) : "memory"); \
    } \
} while (0)

// ---------------- conversion kernels ----------------------------------------
__global__ __launch_bounds__(256) void convert_w_kernel(const int* __restrict__ qw) {
    size_t idx = (size_t)blockIdx.x * blockDim.x + threadIdx.x;  // one int4 (4 weights)
    const int4 v = reinterpret_cast<const int4*>(qw)[idx];
    __half2* w2 = reinterpret_cast<__half2*>(g_w);
    w2[2 * idx + 0] = __floats2half2_rn((float)v.x, (float)v.y);
    w2[2 * idx + 1] = __floats2half2_rn((float)v.z, (float)v.w);
}

__global__ __launch_bounds__(256) void convert_x_kernel(const float* __restrict__ x) {
    size_t idx = (size_t)blockIdx.x * blockDim.x + threadIdx.x;  // one float4
    const float4 v = reinterpret_cast<const float4*>(x)[idx];
    __half2* xh2 = reinterpret_cast<__half2*>(g_xh);
    xh2[2 * idx + 0] = __floats2half2_rn(v.x, v.y);
    xh2[2 * idx + 1] = __floats2half2_rn(v.z, v.w);
}

// ---------------- GEMM kernel ------------------------------------------------
__global__ __launch_bounds__(256, 1) void gemm_kernel(
    float* __restrict__ out,
    const float* __restrict__ swp,
    const float* __restrict__ bias) {
    extern __shared__ char smem[];
    __shared__ unsigned long long mb_full[STAGES];
    __shared__ unsigned long long mb_empty[STAGES];

    const int tid = threadIdx.x;
    const int lane = tid & 31;
    const int wid = tid >> 5;
    const int wm = (wid & 1) * 64;   // warp m offset within CTA (2 warps in m)
    const int wn = (wid >> 1) * 64;  // warp n offset within CTA (4 warps in n)
    const int m0 = blockIdx.y * BM;
    const int n0 = blockIdx.x * BN;

    const uint32_t sbase = (uint32_t)__cvta_generic_to_shared(smem);
    uint32_t full_a[STAGES], empty_a[STAGES];
#pragma unroll
    for (int s = 0; s < STAGES; ++s) {
        full_a[s] = (uint32_t)__cvta_generic_to_shared(&mb_full[s]);
        empty_a[s] = (uint32_t)__cvta_generic_to_shared(&mb_empty[s]);
    }

    if (tid == 0) {
#pragma unroll
        for (int s = 0; s < STAGES; ++s) {
            MBAR_INIT(full_a[s], 256);  // one NOINC completion-arrive per thread
            MBAR_INIT(empty_a[s], 8);   // one arrive per consumer warp
        }
    }
    __syncthreads();

    const __half* gA = g_xh + (size_t)m0 * KDIM;
    const __half* gW = g_w + (size_t)n0 * KDIM;

    float acc[4][8][4];
#pragma unroll
    for (int mi = 0; mi < 4; ++mi)
#pragma unroll
        for (int n = 0; n < 8; ++n)
#pragma unroll
            for (int j = 0; j < 4; ++j) acc[mi][n][j] = 0.f;

    // Per-thread LDSM base offsets
    const uint32_t a_row_off = (lane & 15) * ROW_BYTES + (lane >> 4) * 16;        // +k*2
    const uint32_t b_row_off = (((lane >> 4) & 1) * 8 + (lane & 7)) * ROW_BYTES
                               + (((lane >> 3) & 1) * 8) * 2;                      // +k*2

    // ---- producer body: cp.async tile `it` into stage `s`, noinc-arrive full
    auto produce = [&](int it, int s) {
        const int k0 = it * BK;
        const uint32_t As = sbase + s * STAGE_BYTES;
        const uint32_t Bs = As + A_STAGE_BYTES;
#pragma unroll
        for (int i = 0; i < 4; ++i) {           // A: 1024 16B chunks, 4/thread
            const int c = tid + i * 256;
            const int r = c >> 3, cc = c & 7;
            const uint32_t d = As + r * ROW_BYTES + cc * 16;
            const size_t gsrc = __cvta_generic_to_global(gA + (size_t)r * KDIM + k0 + cc * 8);
            asm volatile("cp.async.cg.shared.global [%0], [%1], 16;"
                         :: "r"(d), "l"(gsrc) : "memory");
        }
#pragma unroll
        for (int i = 0; i < 8; ++i) {           // B: 2048 chunks, 8/thread
            const int c = tid + i * 256;
            const int r = c >> 3, cc = c & 7;
            const uint32_t d = Bs + r * ROW_BYTES + cc * 16;
            const size_t gsrc = __cvta_generic_to_global(gW + (size_t)r * KDIM + k0 + cc * 8);
            asm volatile("cp.async.cg.shared.global [%0], [%1], 16;"
                         :: "r"(d), "l"(gsrc) : "memory");
        }
        CPASYNC_MBAR_ARRIVE_NOINC(full_a[s]);
    };

    auto load_frags = [&](uint32_t As, uint32_t Bs, int ks, uint32_t a[4][4], uint32_t b[4][4]) {
        const uint32_t kb = ks * 32;  // bytes along k
#pragma unroll
        for (int mi = 0; mi < 4; ++mi) {
            const uint32_t ad = As + (wm + mi * 16) * ROW_BYTES + a_row_off + kb;
            asm volatile("ldmatrix.sync.aligned.m8n8.x4.shared.b16 {%0,%1,%2,%3}, [%4];"
                         : "=r"(a[mi][0]), "=r"(a[mi][1]), "=r"(a[mi][2]), "=r"(a[mi][3])
                         : "r"(ad));
        }
#pragma unroll
        for (int nj = 0; nj < 4; ++nj) {
            const uint32_t bd = Bs + (wn + nj * 16) * ROW_BYTES + b_row_off + kb;
            asm volatile("ldmatrix.sync.aligned.m8n8.x4.shared.b16 {%0,%1,%2,%3}, [%4];"
                         : "=r"(b[nj][0]), "=r"(b[nj][1]), "=r"(b[nj][2]), "=r"(b[nj][3])
                         : "r"(bd));
        }
    };

    auto do_mmas = [&](uint32_t a[4][4], uint32_t b[4][4]) {
#pragma unroll
        for (int mi = 0; mi < 4; ++mi) {
#pragma unroll
            for (int n = 0; n < 8; ++n) {
                float* c = acc[mi][n];
                const uint32_t b0 = b[n >> 1][(n & 1) * 2];
                const uint32_t b1 = b[n >> 1][(n & 1) * 2 + 1];
                asm volatile(
                    "mma.sync.aligned.m16n8k16.row.col.f32.f16.f16.f32 "
                    "{%0,%1,%2,%3}, {%4,%5,%6,%7}, {%8,%9}, {%0,%1,%2,%3};"
                    : "+f"(c[0]), "+f"(c[1]), "+f"(c[2]), "+f"(c[3])
                    : "r"(a[mi][0]), "r"(a[mi][1]), "r"(a[mi][2]), "r"(a[mi][3]),
                      "r"(b0), "r"(b1));
            }
        }
    };

    // ---- prologue: producer cursor parity 1 (fresh-barrier wait passes) -----
    int p_stage = 0, p_phase = 1;
#pragma unroll
    for (int it = 0; it < STAGES - 1; ++it) {
        MBAR_WAIT_PARITY(empty_a[p_stage], p_phase);  // passes immediately round 0
        produce(it, p_stage);
        if (++p_stage == STAGES) { p_stage = 0; p_phase ^= 1; }
    }

    uint32_t afrag[2][4][4], bfrag[2][4][4];
    int c_stage = 0, c_phase = 0;

    // ---- mainloop: no __syncthreads; per-stage mbarrier flow control --------
    for (int it = 0; it < KITERS; ++it) {
        MBAR_WAIT_PARITY(full_a[c_stage], c_phase);

        const uint32_t As = sbase + c_stage * STAGE_BYTES;
        const uint32_t Bs = As + A_STAGE_BYTES;

        load_frags(As, Bs, 0, afrag[0], bfrag[0]);
#pragma unroll
        for (int ks = 0; ks < BK / 16; ++ks) {
            if (ks < BK / 16 - 1)
                load_frags(As, Bs, ks + 1, afrag[(ks + 1) & 1], bfrag[(ks + 1) & 1]);
            do_mmas(afrag[ks & 1], bfrag[ks & 1]);
        }

        __syncwarp();
        if (lane == 0) MBAR_ARRIVE(empty_a[c_stage]);   // release stage (count 8)
        if (++c_stage == STAGES) { c_stage = 0; c_phase ^= 1; }

        const int nt = it + (STAGES - 1);
        if (nt < KITERS) {
            MBAR_WAIT_PARITY(empty_a[p_stage], p_phase);
            produce(nt, p_stage);
            if (++p_stage == STAGES) { p_stage = 0; p_phase ^= 1; }
        }
    }

    // ---- epilogue: out = acc*sw + bias --------------------------------------
    const float swv = *swp;
#pragma unroll
    for (int mi = 0; mi < 4; ++mi) {
        const int mr = m0 + wm + mi * 16 + (lane >> 2);
        float* r0 = out + (size_t)mr * NDIM;
        float* r1 = out + (size_t)(mr + 8) * NDIM;
#pragma unroll
        for (int n = 0; n < 8; ++n) {
            const int nc = n0 + wn + n * 8 + (lane & 3) * 2;
            const float2 bv = *reinterpret_cast<const float2*>(bias + nc);
            float2 v0, v1;
            v0.x = acc[mi][n][0] * swv + bv.x;
            v0.y = acc[mi][n][1] * swv + bv.y;
            v1.x = acc[mi][n][2] * swv + bv.x;
            v1.y = acc[mi][n][3] * swv + bv.y;
            *reinterpret_cast<float2*>(r0 + nc) = v0;
            *reinterpret_cast<float2*>(r1 + nc) = v1;
        }
    }
}

// ---------------- launch -----------------------------------------------------
extern "C" void kernel_launch(void* const* d_in, const int* in_sizes, int n_in,
                              void* d_out, int out_size) {
    const float* x = (const float*)d_in[0];
    const int* qw = (const int*)d_in[1];
    const float* sw = (const float*)d_in[2];
    const float* bias = (const float*)d_in[3];
    float* out = (float*)d_out;
    (void)in_sizes; (void)n_in; (void)out_size;

    cudaFuncSetAttribute(gemm_kernel, cudaFuncAttributeMaxDynamicSharedMemorySize, SMEM_TOTAL);

    convert_w_kernel<<<(NDIM * (size_t)KDIM) / 4 / 256, 256>>>(qw);
    convert_x_kernel<<<((size_t)MDIM * KDIM) / 4 / 256, 256>>>(x);

    dim3 grid(NDIM / BN, MDIM / BM);  // (16, 64)
    gemm_kernel<<<grid, 256, SMEM_TOTAL>>>(out, sw, bias);
}

// round 13
// speedup vs baseline: 6.2529x; 1.1238x over previous
#include <cuda_runtime.h>
#include <cuda_fp16.h>
#include <cstdint>

// ============================================================================
// y[M,N] = x[M,K] @ (qw*sw)^T + bias   M=8192, N=4096, K=4096
// x fp32, qw int32 (int8 values), sw fp32 scalar, bias fp32[N], out fp32.
//
// compute_103 target (no tcgen05) => mma.sync.m16n8k16 fp16 / fp32 accum.
// Weights EXACT in fp16 (|q|<=128); x->fp16 gives rel_err ~2e-4 < 1e-3.
//
// R10 vs R9 (706.7us): 2 CTAs/SM for 4 warps/SMSP latency hiding.
//   BN 256->128, STAGES 4->3 => smem/CTA 110592B, launch_bounds(256,2).
//   Warp tile 64x32; frag double-buffer dropped (reg budget 128, cross-warp
//   overlap takes over). mbarrier pipeline (noinc) unchanged from R9.
// ============================================================================

#define MDIM 8192
#define NDIM 4096
#define KDIM 4096

#define BM 128
#define BN 128
#define BK 64
#define STAGES 3
#define KITERS (KDIM / BK)          // 64

#define ROW_HALFS (BK + 8)           // 72 halfs = 144 B (conflict-free ldmatrix)
#define ROW_BYTES (ROW_HALFS * 2)
#define A_STAGE_BYTES (BM * ROW_BYTES)             // 18432
#define B_STAGE_BYTES (BN * ROW_BYTES)             // 18432
#define STAGE_BYTES (A_STAGE_BYTES + B_STAGE_BYTES)  // 36864
#define SMEM_TOTAL (STAGES * STAGE_BYTES)            // 110592 B -> 2 CTAs/SM

// ---------------- scratch (static device globals: allocation-free) ----------
__device__ __half g_xh[(size_t)MDIM * KDIM];  // 64 MB
__device__ __half g_w[(size_t)NDIM * KDIM];   // 32 MB

// ---------------- mbarrier helpers (sm_80+ generic PTX) ----------------------
#define MBAR_INIT(addr, count) \
    asm volatile("mbarrier.init.shared.b64 [%0], %1;" \
        :: "r"((uint32_t)(addr)), "r"((uint32_t)(count)) : "memory")

#define MBAR_ARRIVE(addr) \
    asm volatile("mbarrier.arrive.shared.b64 _, [%0];" :: "r"((uint32_t)(addr)) : "memory")

// NOINC: the completion arrive COUNTS against the init count (256).
#define CPASYNC_MBAR_ARRIVE_NOINC(addr) \
    asm volatile("cp.async.mbarrier.arrive.noinc.shared.b64 [%0];" \
        :: "r"((uint32_t)(addr)) : "memory")

#define MBAR_WAIT_PARITY(mbar_addr, phase_parity) do { \
    uint32_t _mbar = (uint32_t)(mbar_addr); \
    uint32_t _par = (uint32_t)(phase_parity); \
    uint32_t _done; \
    asm volatile( \
        "{\n\t.reg .pred p;\n\t" \
        "mbarrier.try_wait.parity.shared.b64 p, [%1], %2, 0x989680;\n\t" \
        "selp.b32 %0, 1, 0, p;\n\t}" \
        : "=r"(_done) : "r"(_mbar), "r"(_par) : "memory"); \
    if (!_done) { \
        asm volatile( \
            "{\n\t.reg .pred P1;\n\t" \
            "WL_%=:\n\t" \
            "mbarrier.try_wait.parity.shared.b64 P1, [%0], %1, 0x989680;\n\t" \
            "@P1 bra.uni WD_%=;\n\t" \
            "bra.uni WL_%=;\n\t" \
            "WD_%=:\n\t}" \
            :: "r"(_mbar), "r"(_par) : "memory"); \
    } \
} while (0)

// ---------------- conversion kernels ----------------------------------------
__global__ __launch_bounds__(256) void convert_w_kernel(const int* __restrict__ qw) {
    size_t idx = (size_t)blockIdx.x * blockDim.x + threadIdx.x;  // one int4 (4 weights)
    const int4 v = reinterpret_cast<const int4*>(qw)[idx];
    __half2* w2 = reinterpret_cast<__half2*>(g_w);
    w2[2 * idx + 0] = __floats2half2_rn((float)v.x, (float)v.y);
    w2[2 * idx + 1] = __floats2half2_rn((float)v.z, (float)v.w);
}

__global__ __launch_bounds__(256) void convert_x_kernel(const float* __restrict__ x) {
    size_t idx = (size_t)blockIdx.x * blockDim.x + threadIdx.x;  // one float4
    const float4 v = reinterpret_cast<const float4*>(x)[idx];
    __half2* xh2 = reinterpret_cast<__half2*>(g_xh);
    xh2[2 * idx + 0] = __floats2half2_rn(v.x, v.y);
    xh2[2 * idx + 1] = __floats2half2_rn(v.z, v.w);
}

// ---------------- GEMM kernel ------------------------------------------------
__global__ __launch_bounds__(256, 2) void gemm_kernel(
    float* __restrict__ out,
    const float* __restrict__ swp,
    const float* __restrict__ bias) {
    extern __shared__ char smem[];
    __shared__ unsigned long long mb_full[STAGES];
    __shared__ unsigned long long mb_empty[STAGES];

    const int tid = threadIdx.x;
    const int lane = tid & 31;
    const int wid = tid >> 5;
    const int wm = (wid & 1) * 64;   // 2 warps in m, 64 rows each
    const int wn = (wid >> 1) * 32;  // 4 warps in n, 32 cols each
    const int m0 = blockIdx.y * BM;
    const int n0 = blockIdx.x * BN;

    const uint32_t sbase = (uint32_t)__cvta_generic_to_shared(smem);
    uint32_t full_a[STAGES], empty_a[STAGES];
#pragma unroll
    for (int s = 0; s < STAGES; ++s) {
        full_a[s] = (uint32_t)__cvta_generic_to_shared(&mb_full[s]);
        empty_a[s] = (uint32_t)__cvta_generic_to_shared(&mb_empty[s]);
    }

    if (tid == 0) {
#pragma unroll
        for (int s = 0; s < STAGES; ++s) {
            MBAR_INIT(full_a[s], 256);  // one NOINC completion-arrive per thread
            MBAR_INIT(empty_a[s], 8);   // one arrive per consumer warp
        }
    }
    __syncthreads();

    const __half* gA = g_xh + (size_t)m0 * KDIM;
    const __half* gW = g_w + (size_t)n0 * KDIM;

    float acc[4][4][4];
#pragma unroll
    for (int mi = 0; mi < 4; ++mi)
#pragma unroll
        for (int n = 0; n < 4; ++n)
#pragma unroll
            for (int j = 0; j < 4; ++j) acc[mi][n][j] = 0.f;

    // Per-thread LDSM base offsets
    const uint32_t a_row_off = (lane & 15) * ROW_BYTES + (lane >> 4) * 16;        // +k*2
    const uint32_t b_row_off = (((lane >> 4) & 1) * 8 + (lane & 7)) * ROW_BYTES
                               + (((lane >> 3) & 1) * 8) * 2;                      // +k*2

    // ---- producer body: cp.async tile `it` into stage `s`, noinc-arrive full
    auto produce = [&](int it, int s) {
        const int k0 = it * BK;
        const uint32_t As = sbase + s * STAGE_BYTES;
        const uint32_t Bs = As + A_STAGE_BYTES;
#pragma unroll
        for (int i = 0; i < 4; ++i) {           // A: 1024 16B chunks, 4/thread
            const int c = tid + i * 256;
            const int r = c >> 3, cc = c & 7;
            const uint32_t d = As + r * ROW_BYTES + cc * 16;
            const size_t gsrc = __cvta_generic_to_global(gA + (size_t)r * KDIM + k0 + cc * 8);
            asm volatile("cp.async.cg.shared.global [%0], [%1], 16;"
                         :: "r"(d), "l"(gsrc) : "memory");
        }
#pragma unroll
        for (int i = 0; i < 4; ++i) {           // B: 1024 chunks, 4/thread
            const int c = tid + i * 256;
            const int r = c >> 3, cc = c & 7;
            const uint32_t d = Bs + r * ROW_BYTES + cc * 16;
            const size_t gsrc = __cvta_generic_to_global(gW + (size_t)r * KDIM + k0 + cc * 8);
            asm volatile("cp.async.cg.shared.global [%0], [%1], 16;"
                         :: "r"(d), "l"(gsrc) : "memory");
        }
        CPASYNC_MBAR_ARRIVE_NOINC(full_a[s]);
    };

    // ---- mainloop ------------------------------------------------------------
    int p_stage = 0, p_phase = 1;
#pragma unroll
    for (int it = 0; it < STAGES - 1; ++it) {
        MBAR_WAIT_PARITY(empty_a[p_stage], p_phase);  // passes immediately round 0
        produce(it, p_stage);
        if (++p_stage == STAGES) { p_stage = 0; p_phase ^= 1; }
    }

    int c_stage = 0, c_phase = 0;

    for (int it = 0; it < KITERS; ++it) {
        MBAR_WAIT_PARITY(full_a[c_stage], c_phase);

        const uint32_t As = sbase + c_stage * STAGE_BYTES;
        const uint32_t Bs = As + A_STAGE_BYTES;

#pragma unroll
        for (int ks = 0; ks < BK / 16; ++ks) {
            const uint32_t kb = ks * 32;  // bytes along k
            uint32_t a[4][4], b[2][4];
#pragma unroll
            for (int mi = 0; mi < 4; ++mi) {
                const uint32_t ad = As + (wm + mi * 16) * ROW_BYTES + a_row_off + kb;
                asm volatile("ldmatrix.sync.aligned.m8n8.x4.shared.b16 {%0,%1,%2,%3}, [%4];"
                             : "=r"(a[mi][0]), "=r"(a[mi][1]), "=r"(a[mi][2]), "=r"(a[mi][3])
                             : "r"(ad));
            }
#pragma unroll
            for (int nj = 0; nj < 2; ++nj) {
                const uint32_t bd = Bs + (wn + nj * 16) * ROW_BYTES + b_row_off + kb;
                asm volatile("ldmatrix.sync.aligned.m8n8.x4.shared.b16 {%0,%1,%2,%3}, [%4];"
                             : "=r"(b[nj][0]), "=r"(b[nj][1]), "=r"(b[nj][2]), "=r"(b[nj][3])
                             : "r"(bd));
            }
#pragma unroll
            for (int mi = 0; mi < 4; ++mi) {
#pragma unroll
                for (int n = 0; n < 4; ++n) {
                    float* c = acc[mi][n];
                    const uint32_t b0 = b[n >> 1][(n & 1) * 2];
                    const uint32_t b1 = b[n >> 1][(n & 1) * 2 + 1];
                    asm volatile(
                        "mma.sync.aligned.m16n8k16.row.col.f32.f16.f16.f32 "
                        "{%0,%1,%2,%3}, {%4,%5,%6,%7}, {%8,%9}, {%0,%1,%2,%3};"
                        : "+f"(c[0]), "+f"(c[1]), "+f"(c[2]), "+f"(c[3])
                        : "r"(a[mi][0]), "r"(a[mi][1]), "r"(a[mi][2]), "r"(a[mi][3]),
                          "r"(b0), "r"(b1));
                }
            }
        }

        __syncwarp();
        if (lane == 0) MBAR_ARRIVE(empty_a[c_stage]);   // release stage (count 8)
        if (++c_stage == STAGES) { c_stage = 0; c_phase ^= 1; }

        const int nt = it + (STAGES - 1);
        if (nt < KITERS) {
            MBAR_WAIT_PARITY(empty_a[p_stage], p_phase);
            produce(nt, p_stage);
            if (++p_stage == STAGES) { p_stage = 0; p_phase ^= 1; }
        }
    }

    // ---- epilogue: out = acc*sw + bias --------------------------------------
    const float swv = *swp;
#pragma unroll
    for (int mi = 0; mi < 4; ++mi) {
        const int mr = m0 + wm + mi * 16 + (lane >> 2);
        float* r0 = out + (size_t)mr * NDIM;
        float* r1 = out + (size_t)(mr + 8) * NDIM;
#pragma unroll
        for (int n = 0; n < 4; ++n) {
            const int nc = n0 + wn + n * 8 + (lane & 3) * 2;
            const float2 bv = *reinterpret_cast<const float2*>(bias + nc);
            float2 v0, v1;
            v0.x = acc[mi][n][0] * swv + bv.x;
            v0.y = acc[mi][n][1] * swv + bv.y;
            v1.x = acc[mi][n][2] * swv + bv.x;
            v1.y = acc[mi][n][3] * swv + bv.y;
            *reinterpret_cast<float2*>(r0 + nc) = v0;
            *reinterpret_cast<float2*>(r1 + nc) = v1;
        }
    }
}

// ---------------- launch -----------------------------------------------------
extern "C" void kernel_launch(void* const* d_in, const int* in_sizes, int n_in,
                              void* d_out, int out_size) {
    const float* x = (const float*)d_in[0];
    const int* qw = (const int*)d_in[1];
    const float* sw = (const float*)d_in[2];
    const float* bias = (const float*)d_in[3];
    float* out = (float*)d_out;
    (void)in_sizes; (void)n_in; (void)out_size;

    cudaFuncSetAttribute(gemm_kernel, cudaFuncAttributeMaxDynamicSharedMemorySize, SMEM_TOTAL);

    convert_w_kernel<<<(NDIM * (size_t)KDIM) / 4 / 256, 256>>>(qw);
    convert_x_kernel<<<((size_t)MDIM * KDIM) / 4 / 256, 256>>>(x);

    dim3 grid(NDIM / BN, MDIM / BM);  // (32, 64)
    gemm_kernel<<<grid, 256, SMEM_TOTAL>>>(out, sw, bias);
}